// round 12
// baseline (speedup 1.0000x reference)
#include <cuda_runtime.h>
#include <cuda_pipeline.h>
#include <cstdint>

#define B        2
#define N_PRE    50000
#define N_POST   50000
#define N_SYN    10000000
#define N_TYPES  20
#define N_BASIS  5

#define MASK_WORDS (N_PRE / 16)          // 3125 words (2 bits/neuron)
#define N_ROWS     (B * N_POST)          // 100000

#define CHUNK_SYN   1024                 // synapses per staged chunk
#define CHUNK_INT4  (CHUNK_SYN / 2)      // 512 int4 = 8 KB
#define NCHUNK      (N_SYN / CHUNK_SYN)  // 9765 full chunks
#define TAIL_START  (NCHUNK * CHUNK_SYN) // 9,999,360
#define ACC_GRID    1036                 // 148 SMs * 7 blocks

__device__ uint32_t g_spike_mask[MASK_WORDS];
// Per-(batch,post) x type weight sums. Zero at module load; compact_kernel
// re-zeroes after reading, so it is zero at entry of EVERY kernel_launch call.
__device__ __align__(16) float g_S[N_ROWS * N_TYPES];   // 8 MB, L2-resident

// ---------------------------------------------------------------------------
// prep: ballot-based packed 2-bit spike mask.
__global__ void prep_kernel(const float* __restrict__ spikes)
{
    int tid = blockIdx.x * blockDim.x + threadIdx.x;
    if (tid >= ((N_PRE + 31) & ~31)) return;
    int n = tid;
    bool f0 = false, f1 = false;
    if (n < N_PRE) {
        f0 = (__ldg(spikes + n) != 0.0f);
        f1 = (__ldg(spikes + N_PRE + n) != 0.0f);
    }
    uint32_t b0 = __ballot_sync(0xFFFFFFFFu, f0);
    uint32_t b1 = __ballot_sync(0xFFFFFFFFu, f1);
    int lane = threadIdx.x & 31;
    if (lane == 0 || lane == 16) {
        uint32_t h0 = (b0 >> lane) & 0xFFFFu;
        uint32_t h1 = (b1 >> lane) & 0xFFFFu;
        uint32_t m = 0;
        #pragma unroll
        for (int j = 0; j < 16; j++)
            m |= (((h0 >> j) & 1u) | (((h1 >> j) & 1u) << 1)) << (2 * j);
        int w = (n >> 4);
        if (w < MASK_WORDS) g_spike_mask[w] = m;
    }
}

// ---------------------------------------------------------------------------
// Heavy path for 4 synapses given masks + base synapse index s.
__device__ __forceinline__ void emit4(uint32_t m0, uint32_t m1, uint32_t m2,
                                      uint32_t m3, int p0, int p1, int p2, int p3,
                                      int s,
                                      const float* __restrict__ weights,
                                      const int4*  __restrict__ syn_ids4)
{
    float4 wv = __ldg((const float4*)(weights + s));
    int4   tt = __ldg(syn_ids4 + (s >> 2));

    float* r0 = g_S + (size_t)p0 * N_TYPES + tt.x;
    float* r1 = g_S + (size_t)p1 * N_TYPES + tt.y;
    float* r2 = g_S + (size_t)p2 * N_TYPES + tt.z;
    float* r3 = g_S + (size_t)p3 * N_TYPES + tt.w;
    const size_t OFF = (size_t)N_POST * N_TYPES;

    if (m0 & 1u) atomicAdd(r0,       wv.x);
    if (m0 & 2u) atomicAdd(r0 + OFF, wv.x);
    if (m1 & 1u) atomicAdd(r1,       wv.y);
    if (m1 & 2u) atomicAdd(r1 + OFF, wv.y);
    if (m2 & 1u) atomicAdd(r2,       wv.z);
    if (m2 & 2u) atomicAdd(r2 + OFF, wv.z);
    if (m3 & 1u) atomicAdd(r3,       wv.w);
    if (m3 & 2u) atomicAdd(r3 + OFF, wv.w);
}

__global__ __launch_bounds__(256)
void accum_kernel(const float* __restrict__ weights,       // [N_SYN]
                  const int4*  __restrict__ syn_idx4,      // [N_SYN/2]
                  const int4*  __restrict__ syn_ids4)      // [N_SYN/4]
{
    __shared__ uint32_t smask[MASK_WORDS];
    __shared__ __align__(16) int4 sidx[2][CHUNK_INT4];     // 2 x 8 KB

    const int tid = threadIdx.x;
    const unsigned grid = gridDim.x;

    // Start streaming the index chunks BEFORE waiting on prep: the stream
    // does not depend on the spike mask.
    int ck = blockIdx.x;
    if (ck < NCHUNK) {
        const int4* src = syn_idx4 + (size_t)ck * CHUNK_INT4;
        __pipeline_memcpy_async(&sidx[0][tid * 2],     src + tid * 2,     16);
        __pipeline_memcpy_async(&sidx[0][tid * 2 + 1], src + tid * 2 + 1, 16);
    }
    __pipeline_commit();

    // Now wait for prep (PDL) and pull the mask into smem.
    cudaGridDependencySynchronize();
    for (int i = tid; i < MASK_WORDS; i += blockDim.x)
        smask[i] = g_spike_mask[i];
    __syncthreads();

    int buf = 0;
    for (; ck < NCHUNK; ck += grid) {
        // Prefetch next chunk into the other buffer (overwrites the buffer
        // processed LAST iteration; the trailing __syncthreads covers it).
        int nk = ck + grid;
        if (nk < NCHUNK) {
            const int4* src = syn_idx4 + (size_t)nk * CHUNK_INT4;
            __pipeline_memcpy_async(&sidx[buf ^ 1][tid * 2],     src + tid * 2,     16);
            __pipeline_memcpy_async(&sidx[buf ^ 1][tid * 2 + 1], src + tid * 2 + 1, 16);
        }
        __pipeline_commit();
        __pipeline_wait_prior(1);     // current chunk's data has landed
        __syncthreads();

        // Process 4 synapses per thread from smem.
        int4 u = sidx[buf][tid * 2];
        int4 v = sidx[buf][tid * 2 + 1];

        uint32_t m0 = (smask[u.y >> 4] >> ((u.y & 15) << 1)) & 3u;
        uint32_t m1 = (smask[u.w >> 4] >> ((u.w & 15) << 1)) & 3u;
        uint32_t m2 = (smask[v.y >> 4] >> ((v.y & 15) << 1)) & 3u;
        uint32_t m3 = (smask[v.w >> 4] >> ((v.w & 15) << 1)) & 3u;

        if ((m0 | m1 | m2 | m3) != 0u) {
            int s = ck * CHUNK_SYN + tid * 4;
            emit4(m0, m1, m2, m3, u.x, u.z, v.x, v.z, s, weights, syn_ids4);
        }

        __syncthreads();              // all reads of sidx[buf] done
        buf ^= 1;
    }

    // Tail: 640 synapses via direct loads, block 0 only.
    if (blockIdx.x == 0) {
        int g = TAIL_START / 4 + tid;            // 4 synapses per thread
        if (g < N_SYN / 4) {
            int4 u = __ldg(syn_idx4 + g * 2);
            int4 v = __ldg(syn_idx4 + g * 2 + 1);
            uint32_t m0 = (smask[u.y >> 4] >> ((u.y & 15) << 1)) & 3u;
            uint32_t m1 = (smask[u.w >> 4] >> ((u.w & 15) << 1)) & 3u;
            uint32_t m2 = (smask[v.y >> 4] >> ((v.y & 15) << 1)) & 3u;
            uint32_t m3 = (smask[v.w >> 4] >> ((v.w & 15) << 1)) & 3u;
            if ((m0 | m1 | m2 | m3) != 0u)
                emit4(m0, m1, m2, m3, u.x, u.z, v.x, v.z, g * 4, weights, syn_ids4);
        }
    }
}

// ---------------------------------------------------------------------------
// compact: out[row][r] = sum_t S[row][t] * basis[t][r]; then zero S[row].
__global__ __launch_bounds__(256)
void compact_kernel(const float* __restrict__ basis, float* __restrict__ out)
{
    __shared__ float sb[N_TYPES * N_BASIS];
    __shared__ float srow[256 * N_BASIS];

    int tid = threadIdx.x;
    if (tid < N_TYPES * N_BASIS) sb[tid] = basis[tid];
    __syncthreads();

    cudaGridDependencySynchronize();   // wait for accum before touching g_S

    int row = blockIdx.x * 256 + tid;
    if (row < N_ROWS) {
        float4* S4 = (float4*)(g_S + (size_t)row * N_TYPES);
        float4 a = S4[0], b = S4[1], c = S4[2], d = S4[3], e = S4[4];
        float s[N_TYPES] = {a.x,a.y,a.z,a.w, b.x,b.y,b.z,b.w, c.x,c.y,c.z,c.w,
                            d.x,d.y,d.z,d.w, e.x,e.y,e.z,e.w};
        #pragma unroll
        for (int r = 0; r < N_BASIS; r++) {
            float acc = 0.f;
            #pragma unroll
            for (int t = 0; t < N_TYPES; t++)
                acc += s[t] * sb[t * N_BASIS + r];
            srow[tid * N_BASIS + r] = acc;
        }
        float4 z = make_float4(0.f, 0.f, 0.f, 0.f);
        S4[0] = z; S4[1] = z; S4[2] = z; S4[3] = z; S4[4] = z;
    }
    __syncthreads();

    const int total4 = (N_ROWS * N_BASIS) / 4;
    int base4 = blockIdx.x * 320;
    float4* out4 = (float4*)out;
    for (int i = tid; i < 320; i += 256) {
        int o4 = base4 + i;
        if (o4 < total4) {
            const float* p = srow + i * 4;
            out4[o4] = make_float4(p[0], p[1], p[2], p[3]);
        }
    }
}

extern "C" void kernel_launch(void* const* d_in, const int* in_sizes, int n_in,
                              void* d_out, int out_size)
{
    const float* spikes  = (const float*)d_in[0];
    const float* weights = (const float*)d_in[1];
    const float* basis   = (const float*)d_in[2];
    const int4*  syn_idx = (const int4*)d_in[3];
    const int4*  syn_ids = (const int4*)d_in[4];
    float* out = (float*)d_out;

    prep_kernel<<<196, 256>>>(spikes);

    {
        cudaLaunchAttribute attr[1];
        attr[0].id = cudaLaunchAttributeProgrammaticStreamSerialization;
        attr[0].val.programmaticStreamSerializationAllowed = 1;
        cudaLaunchConfig_t cfg = {};
        cfg.gridDim  = dim3(ACC_GRID, 1, 1);
        cfg.blockDim = dim3(256, 1, 1);
        cfg.stream = 0;
        cfg.attrs = attr;
        cfg.numAttrs = 1;
        cudaLaunchKernelEx(&cfg, accum_kernel, weights, syn_idx, syn_ids);
    }

    {
        cudaLaunchAttribute attr[1];
        attr[0].id = cudaLaunchAttributeProgrammaticStreamSerialization;
        attr[0].val.programmaticStreamSerializationAllowed = 1;
        cudaLaunchConfig_t cfg = {};
        cfg.gridDim  = dim3((N_ROWS + 255) / 256, 1, 1);
        cfg.blockDim = dim3(256, 1, 1);
        cfg.stream = 0;
        cfg.attrs = attr;
        cfg.numAttrs = 1;
        cudaLaunchKernelEx(&cfg, compact_kernel, basis, out);
    }
}

// round 13
// speedup vs baseline: 1.1979x; 1.1979x over previous
#include <cuda_runtime.h>
#include <cstdint>

#define B        2
#define N_PRE    50000
#define N_POST   50000
#define N_SYN    10000000
#define N_TYPES  20
#define N_BASIS  5

#define MASK_WORDS (N_PRE / 16)          // 3125 words (2 bits/neuron)
#define N_ROWS     (B * N_POST)          // 100000

__device__ uint32_t g_spike_mask[MASK_WORDS];
// Per-(batch,post) x type weight sums. Zero at module load; compact_kernel
// re-zeroes after reading, so it is zero at entry of EVERY kernel_launch call.
__device__ __align__(16) float g_S[N_ROWS * N_TYPES];   // 8 MB, L2-resident

// ---------------------------------------------------------------------------
// prep: ballot-based packed 2-bit spike mask.
__global__ void prep_kernel(const float* __restrict__ spikes)
{
    int tid = blockIdx.x * blockDim.x + threadIdx.x;
    if (tid >= ((N_PRE + 31) & ~31)) return;
    int n = tid;
    bool f0 = false, f1 = false;
    if (n < N_PRE) {
        f0 = (__ldg(spikes + n) != 0.0f);
        f1 = (__ldg(spikes + N_PRE + n) != 0.0f);
    }
    uint32_t b0 = __ballot_sync(0xFFFFFFFFu, f0);
    uint32_t b1 = __ballot_sync(0xFFFFFFFFu, f1);
    int lane = threadIdx.x & 31;
    if (lane == 0 || lane == 16) {
        uint32_t h0 = (b0 >> lane) & 0xFFFFu;
        uint32_t h1 = (b1 >> lane) & 0xFFFFu;
        uint32_t m = 0;
        #pragma unroll
        for (int j = 0; j < 16; j++)
            m |= (((h0 >> j) & 1u) | (((h1 >> j) & 1u) << 1)) << (2 * j);
        int w = (n >> 4);
        if (w < MASK_WORDS) g_spike_mask[w] = m;
    }
}

// ---------------------------------------------------------------------------
__global__ __launch_bounds__(256)
void accum_kernel(const float* __restrict__ weights,       // [N_SYN]
                  const int4*  __restrict__ syn_idx4,      // [N_SYN/2]
                  const int4*  __restrict__ syn_ids4)      // [N_SYN/4]
{
    __shared__ uint32_t smask[MASK_WORDS];

    cudaGridDependencySynchronize();   // wait for prep (PDL)

    for (int i = threadIdx.x; i < MASK_WORDS; i += blockDim.x)
        smask[i] = g_spike_mask[i];
    __syncthreads();

    const int NG = N_SYN / 4;                 // 4 consecutive synapses / thread
    const int stride = gridDim.x * blockDim.x;
    const size_t OFF = (size_t)N_POST * N_TYPES;

    int g = blockIdx.x * blockDim.x + threadIdx.x;
    bool valid = (g < NG);
    int4 u, v;
    if (valid) {
        u = __ldcs(syn_idx4 + g * 2);
        v = __ldcs(syn_idx4 + g * 2 + 1);
    }

    while (valid) {
        // Software pipeline: issue NEXT iteration's stream loads first so
        // they overlap this iteration's mask lookups / heavy path.
        int gn = g + stride;
        bool nvalid = (gn < NG);
        int4 un, vn;
        if (nvalid) {
            un = __ldcs(syn_idx4 + gn * 2);
            vn = __ldcs(syn_idx4 + gn * 2 + 1);
        }

        uint32_t m0 = (smask[u.y >> 4] >> ((u.y & 15) << 1)) & 3u;
        uint32_t m1 = (smask[u.w >> 4] >> ((u.w & 15) << 1)) & 3u;
        uint32_t m2 = (smask[v.y >> 4] >> ((v.y & 15) << 1)) & 3u;
        uint32_t m3 = (smask[v.w >> 4] >> ((v.w & 15) << 1)) & 3u;

        if ((m0 | m1 | m2 | m3) != 0u) {       // ~15% of lanes
            float4 wv = __ldg((const float4*)(weights + g * 4));
            int4   tt = __ldg(syn_ids4 + g);

            float* r0 = g_S + (size_t)u.x * N_TYPES + tt.x;
            float* r1 = g_S + (size_t)u.z * N_TYPES + tt.y;
            float* r2 = g_S + (size_t)v.x * N_TYPES + tt.z;
            float* r3 = g_S + (size_t)v.z * N_TYPES + tt.w;

            if (m0 & 1u) atomicAdd(r0,       wv.x);
            if (m0 & 2u) atomicAdd(r0 + OFF, wv.x);
            if (m1 & 1u) atomicAdd(r1,       wv.y);
            if (m1 & 2u) atomicAdd(r1 + OFF, wv.y);
            if (m2 & 1u) atomicAdd(r2,       wv.z);
            if (m2 & 2u) atomicAdd(r2 + OFF, wv.z);
            if (m3 & 1u) atomicAdd(r3,       wv.w);
            if (m3 & 2u) atomicAdd(r3 + OFF, wv.w);
        }

        g = gn; valid = nvalid; u = un; v = vn;
    }
}

// ---------------------------------------------------------------------------
// compact: out[row][r] = sum_t S[row][t] * basis[t][r]; then zero S[row].
__global__ __launch_bounds__(256)
void compact_kernel(const float* __restrict__ basis, float* __restrict__ out)
{
    __shared__ float sb[N_TYPES * N_BASIS];
    __shared__ float srow[256 * N_BASIS];

    int tid = threadIdx.x;
    if (tid < N_TYPES * N_BASIS) sb[tid] = basis[tid];
    __syncthreads();

    cudaGridDependencySynchronize();   // wait for accum before touching g_S

    int row = blockIdx.x * 256 + tid;
    if (row < N_ROWS) {
        float4* S4 = (float4*)(g_S + (size_t)row * N_TYPES);
        float4 a = S4[0], b = S4[1], c = S4[2], d = S4[3], e = S4[4];
        float s[N_TYPES] = {a.x,a.y,a.z,a.w, b.x,b.y,b.z,b.w, c.x,c.y,c.z,c.w,
                            d.x,d.y,d.z,d.w, e.x,e.y,e.z,e.w};
        #pragma unroll
        for (int r = 0; r < N_BASIS; r++) {
            float acc = 0.f;
            #pragma unroll
            for (int t = 0; t < N_TYPES; t++)
                acc += s[t] * sb[t * N_BASIS + r];
            srow[tid * N_BASIS + r] = acc;
        }
        float4 z = make_float4(0.f, 0.f, 0.f, 0.f);
        S4[0] = z; S4[1] = z; S4[2] = z; S4[3] = z; S4[4] = z;
    }
    __syncthreads();

    const int total4 = (N_ROWS * N_BASIS) / 4;
    int base4 = blockIdx.x * 320;
    float4* out4 = (float4*)out;
    for (int i = tid; i < 320; i += 256) {
        int o4 = base4 + i;
        if (o4 < total4) {
            const float* p = srow + i * 4;
            out4[o4] = make_float4(p[0], p[1], p[2], p[3]);
        }
    }
}

extern "C" void kernel_launch(void* const* d_in, const int* in_sizes, int n_in,
                              void* d_out, int out_size)
{
    const float* spikes  = (const float*)d_in[0];
    const float* weights = (const float*)d_in[1];
    const float* basis   = (const float*)d_in[2];
    const int4*  syn_idx = (const int4*)d_in[3];
    const int4*  syn_ids = (const int4*)d_in[4];
    float* out = (float*)d_out;

    prep_kernel<<<196, 256>>>(spikes);

    {
        cudaLaunchAttribute attr[1];
        attr[0].id = cudaLaunchAttributeProgrammaticStreamSerialization;
        attr[0].val.programmaticStreamSerializationAllowed = 1;
        cudaLaunchConfig_t cfg = {};
        cfg.gridDim  = dim3(1184, 1, 1);
        cfg.blockDim = dim3(256, 1, 1);
        cfg.stream = 0;
        cfg.attrs = attr;
        cfg.numAttrs = 1;
        cudaLaunchKernelEx(&cfg, accum_kernel, weights, syn_idx, syn_ids);
    }

    {
        cudaLaunchAttribute attr[1];
        attr[0].id = cudaLaunchAttributeProgrammaticStreamSerialization;
        attr[0].val.programmaticStreamSerializationAllowed = 1;
        cudaLaunchConfig_t cfg = {};
        cfg.gridDim  = dim3((N_ROWS + 255) / 256, 1, 1);
        cfg.blockDim = dim3(256, 1, 1);
        cfg.stream = 0;
        cfg.attrs = attr;
        cfg.numAttrs = 1;
        cudaLaunchKernelEx(&cfg, compact_kernel, basis, out);
    }
}